// round 7
// baseline (speedup 1.0000x reference)
#include <cuda_runtime.h>
#include <cuda_fp16.h>
#include <cstdint>

// ---------------------------------------------------------------------------
// Problem shape / tiling
// ---------------------------------------------------------------------------
#define BSZ    16384
#define DDIM   128
#define TILE_M 256               // rows per item
#define TILE_N 128               // cols per tile step
#define PITCH  272               // smem row pitch bytes (256 data + 16 pad)
#define NRT    (BSZ / TILE_M)    // 64 row tiles
#define NCHUNK 16                // col chunks per row tile (1024 cols)
#define NITEMS (NRT * NCHUNK)    // 1024 work items
#define CHUNK_TILES 8
#define GRID_PERS 148
#define NWARPS_G (GRID_PERS * 16)   // 2368 global warps
#define NEGINF_LO 0x0000FC00u
#define NEGINF_HI 0xFC000000u

// Scratch (device globals; allocation-free rule)
__device__ __align__(128) __half g_Qh[BSZ * DDIM];   // 4 MB
__device__ __align__(128) __half g_Dh[BSZ * DDIM];   // 4 MB
__device__ float    g_pos[BSZ];
__device__ float    g_term1[BSZ];
__device__ unsigned g_rowmax_enc[BSZ];
__device__ int      g_ctr;     // work-item counter
__device__ int      g_prep;    // grid barrier (prep done)
__device__ int      g_done;    // grid exit counter

// ---------------------------------------------------------------------------
// helpers
// ---------------------------------------------------------------------------
__device__ __forceinline__ uint32_t smem_to_u32(const void* p) {
    uint32_t a;
    asm("{ .reg .u64 t; cvta.to.shared.u64 t, %1; cvt.u32.u64 %0, t; }" : "=r"(a) : "l"(p));
    return a;
}
__device__ __forceinline__ void cpasync16(uint32_t s, const void* g) {
    asm volatile("cp.async.cg.shared.global [%0], [%1], 16;" :: "r"(s), "l"(g));
}
#define CP_COMMIT() asm volatile("cp.async.commit_group;" ::: "memory")
#define CP_WAIT0()  asm volatile("cp.async.wait_group 0;" ::: "memory")

__device__ __forceinline__ void ldsm4(uint32_t* r, uint32_t addr) {
    asm volatile("ldmatrix.sync.aligned.m8n8.x4.shared.b16 {%0,%1,%2,%3}, [%4];"
                 : "=r"(r[0]), "=r"(r[1]), "=r"(r[2]), "=r"(r[3]) : "r"(addr));
}
__device__ __forceinline__ void mma16816h(uint32_t* c, const uint32_t* a, uint32_t b0, uint32_t b1) {
    asm volatile("mma.sync.aligned.m16n8k16.row.col.f16.f16.f16.f16 "
                 "{%0,%1}, {%2,%3,%4,%5}, {%6,%7}, {%0,%1};"
                 : "+r"(c[0]), "+r"(c[1])
                 : "r"(a[0]), "r"(a[1]), "r"(a[2]), "r"(a[3]), "r"(b0), "r"(b1));
}
__device__ __forceinline__ uint32_t hmax2(uint32_t a, uint32_t b) {
    uint32_t d;
    asm("max.f16x2 %0, %1, %2;" : "=r"(d) : "r"(a), "r"(b));
    return d;
}
__device__ __forceinline__ float softplusf(float x) {
    return x > 20.0f ? x : log1pf(__expf(x));
}
__device__ __forceinline__ unsigned enc_f(float x) {
    unsigned u = __float_as_uint(x);
    return (u & 0x80000000u) ? ~u : (u | 0x80000000u);
}
__device__ __forceinline__ float dec_f(unsigned e) {
    unsigned u = (e & 0x80000000u) ? (e & 0x7FFFFFFFu) : ~e;
    return __uint_as_float(u);
}

// ---------------------------------------------------------------------------
// smem layout
// ---------------------------------------------------------------------------
#define SMEM_A0   0
#define SMEM_A1   (TILE_M * PITCH)                         // 69632
#define SMEM_B0   (2 * TILE_M * PITCH)                     // 139264
#define SMEM_B1   (2 * TILE_M * PITCH + 128 * PITCH)       // 174080
#define SMEM_RED  (2 * TILE_M * PITCH + 2 * 128 * PITCH)   // 208896
#define SMEM_TOTAL (SMEM_RED + TILE_M * 16)                // 212992 B

__device__ __forceinline__ void load_tileA(uint32_t dst, const __half* src,
                                           int rowBase, int tid) {
    const char* s = (const char*)(src + (size_t)rowBase * DDIM);
    #pragma unroll
    for (int i = 0; i < 8; ++i) {
        int e = tid + 512 * i;
        int r = e >> 4;
        int c = e & 15;
        cpasync16(dst + r * PITCH + c * 16, s + (size_t)r * 256 + c * 16);
    }
}
__device__ __forceinline__ void load_tileB(uint32_t dst, const __half* src,
                                           int rowBase, int tid) {
    const char* s = (const char*)(src + (size_t)rowBase * DDIM);
    #pragma unroll
    for (int i = 0; i < 4; ++i) {
        int e = tid + 512 * i;
        int r = e >> 4;
        int c = e & 15;
        cpasync16(dst + r * PITCH + c * 16, s + (size_t)r * 256 + c * 16);
    }
}

// ---------------------------------------------------------------------------
// ONE persistent kernel: prep -> grid barrier -> max-GEMM -> last-CTA finalize
// ---------------------------------------------------------------------------
__global__ void __launch_bounds__(512, 1)
mega_kernel(const float* __restrict__ q, const float* __restrict__ d,
            const float* __restrict__ nd, float* __restrict__ out) {
    extern __shared__ __align__(1024) char smem[];
    __shared__ int s_item;
    const uint32_t sb = smem_to_u32(smem);
    const int tid  = threadIdx.x;
    const int lane = tid & 31;
    const int wid  = tid >> 5;
    const int wm   = wid >> 2;        // 0..3
    const int wn   = wid & 3;         // 0..3

    // ---------------- Phase 0: prep (f32->f16, pairwise dots, init) --------
    {
        int gw = blockIdx.x * 16 + wid;   // global warp id 0..2367
        for (int row = gw; row < BSZ; row += NWARPS_G) {
            const float4 qv = *(const float4*)(q  + (size_t)row * DDIM + lane * 4);
            const float4 dv = *(const float4*)(d  + (size_t)row * DDIM + lane * 4);
            const float4 nv = *(const float4*)(nd + (size_t)row * DDIM + lane * 4);

            __half2* qdst = (__half2*)(g_Qh + (size_t)row * DDIM + lane * 4);
            qdst[0] = __floats2half2_rn(qv.x, qv.y);
            qdst[1] = __floats2half2_rn(qv.z, qv.w);
            __half2* ddst = (__half2*)(g_Dh + (size_t)row * DDIM + lane * 4);
            ddst[0] = __floats2half2_rn(dv.x, dv.y);
            ddst[1] = __floats2half2_rn(dv.z, dv.w);

            float pos = qv.x * dv.x + qv.y * dv.y + qv.z * dv.z + qv.w * dv.w;
            float neg = qv.x * nv.x + qv.y * nv.y + qv.z * nv.z + qv.w * nv.w;
            #pragma unroll
            for (int off = 16; off > 0; off >>= 1) {
                pos += __shfl_xor_sync(0xFFFFFFFFu, pos, off);
                neg += __shfl_xor_sync(0xFFFFFFFFu, neg, off);
            }
            if (lane == 0) {
                g_pos[row]   = pos;
                g_term1[row] = softplusf(neg - pos);
                g_rowmax_enc[row] = 0u;
            }
        }
    }
    // ---------------- grid barrier (148 co-resident CTAs) -------------------
    __threadfence();
    __syncthreads();
    if (tid == 0) {
        atomicAdd(&g_prep, 1);
        while (atomicAdd(&g_prep, 0) < GRID_PERS) { }
    }
    __syncthreads();

    // ---------------- Phase 1: persistent max-GEMM --------------------------
    const uint32_t aOff  = (uint32_t)((wm * 64 + (lane & 15)) * PITCH + (lane & 16));
    const uint32_t bRow  = (uint32_t)(wn * 32 + ((lane >> 4) << 3) + (lane & 7));
    const uint32_t bOffC = (uint32_t)((lane & 8) << 1);
    float* red = (float*)(smem + SMEM_RED);   // [256][4]

    if (tid == 0) s_item = atomicAdd(&g_ctr, 1);
    __syncthreads();
    int cur = s_item;
    int abuf = 0;
    if (cur < NITEMS) {
        load_tileA(sb + SMEM_A0, g_Qh, (cur >> 4) * TILE_M, tid);
        load_tileB(sb + SMEM_B0, g_Dh, ((cur & 15) * CHUNK_TILES) * TILE_N, tid);
        CP_COMMIT();
    }

    while (cur < NITEMS) {
        const int rt = cur >> 4;
        const int cc = cur & 15;
        const int rowBase  = rt * TILE_M;
        const int tileBase = cc * CHUNK_TILES;
        const uint32_t aBase = sb + (abuf ? SMEM_A1 : SMEM_A0) + aOff;

        uint32_t rmax2[4][2];
        #pragma unroll
        for (int mi = 0; mi < 4; ++mi) { rmax2[mi][0] = 0xFC00FC00u; rmax2[mi][1] = 0xFC00FC00u; }

        int nxt = 0;
        for (int j = 0; j < CHUNK_TILES; ++j) {
            CP_WAIT0();
            __syncthreads();
            if (j + 1 < CHUNK_TILES) {
                uint32_t dst = sb + (((j + 1) & 1) ? SMEM_B1 : SMEM_B0);
                load_tileB(dst, g_Dh, (tileBase + j + 1) * TILE_N, tid);
                CP_COMMIT();
                if (j == CHUNK_TILES - 2 && tid == 0) s_item = atomicAdd(&g_ctr, 1);
            } else {
                nxt = s_item;
                if (nxt < NITEMS) {
                    load_tileA(sb + (abuf ? SMEM_A0 : SMEM_A1), g_Qh, (nxt >> 4) * TILE_M, tid);
                    load_tileB(sb + SMEM_B0, g_Dh, ((nxt & 15) * CHUNK_TILES) * TILE_N, tid);
                    CP_COMMIT();
                }
            }
            const uint32_t bBase = sb + ((j & 1) ? SMEM_B1 : SMEM_B0) + bRow * PITCH + bOffC;

            uint32_t acc[4][4][2];
            #pragma unroll
            for (int mi = 0; mi < 4; ++mi)
                #pragma unroll
                for (int ni = 0; ni < 4; ++ni) { acc[mi][ni][0] = 0u; acc[mi][ni][1] = 0u; }

            #pragma unroll
            for (int ks = 0; ks < 8; ++ks) {
                uint32_t a[4][4];
                #pragma unroll
                for (int mi = 0; mi < 4; ++mi)
                    ldsm4(a[mi], aBase + (uint32_t)(mi * 16 * PITCH + ks * 32));
                uint32_t b[2][4];
                #pragma unroll
                for (int np = 0; np < 2; ++np)
                    ldsm4(b[np], bBase + (uint32_t)(np * 16 * PITCH + ks * 32));
                #pragma unroll
                for (int mi = 0; mi < 4; ++mi)
                    #pragma unroll
                    for (int ni = 0; ni < 4; ++ni)
                        mma16816h(acc[mi][ni], a[mi],
                                  b[ni >> 1][(ni & 1) * 2], b[ni >> 1][(ni & 1) * 2 + 1]);
            }

            // diagonal: col tile hits diag when ct == 2*rt (rows 0..127) or 2*rt+1
            const int dt = (tileBase + j) - 2 * rt;
            if (dt == 0 || dt == 1) {
                const int coff = dt * 128;
                #pragma unroll
                for (int mi = 0; mi < 4; ++mi) {
                    int r0 = wm * 64 + mi * 16 + (lane >> 2);
                    #pragma unroll
                    for (int ni = 0; ni < 4; ++ni) {
                        int c0 = wn * 32 + ni * 8 + (lane & 3) * 2 + coff;
                        if (c0     == r0)     acc[mi][ni][0] = (acc[mi][ni][0] & 0xFFFF0000u) | NEGINF_LO;
                        if (c0 + 1 == r0)     acc[mi][ni][0] = (acc[mi][ni][0] & 0x0000FFFFu) | NEGINF_HI;
                        if (c0     == r0 + 8) acc[mi][ni][1] = (acc[mi][ni][1] & 0xFFFF0000u) | NEGINF_LO;
                        if (c0 + 1 == r0 + 8) acc[mi][ni][1] = (acc[mi][ni][1] & 0x0000FFFFu) | NEGINF_HI;
                    }
                }
            }
            #pragma unroll
            for (int mi = 0; mi < 4; ++mi)
                #pragma unroll
                for (int ni = 0; ni < 4; ++ni) {
                    rmax2[mi][0] = hmax2(rmax2[mi][0], acc[mi][ni][0]);
                    rmax2[mi][1] = hmax2(rmax2[mi][1], acc[mi][ni][1]);
                }
        }

        // epilogue: collapse + cross-warp reduce + atomicMax merge
        float rmax[8];
        #pragma unroll
        for (int mi = 0; mi < 4; ++mi)
            #pragma unroll
            for (int rr = 0; rr < 2; ++rr) {
                __half2 h = *(__half2*)&rmax2[mi][rr];
                rmax[mi * 2 + rr] = fmaxf(__low2float(h), __high2float(h));
            }
        #pragma unroll
        for (int i = 0; i < 8; ++i) {
            rmax[i] = fmaxf(rmax[i], __shfl_xor_sync(0xFFFFFFFFu, rmax[i], 1));
            rmax[i] = fmaxf(rmax[i], __shfl_xor_sync(0xFFFFFFFFu, rmax[i], 2));
        }
        __syncthreads();
        if ((lane & 3) == 0) {
            #pragma unroll
            for (int mi = 0; mi < 4; ++mi) {
                int rA = wm * 64 + mi * 16 + (lane >> 2);
                red[rA * 4 + wn]       = rmax[mi * 2 + 0];
                red[(rA + 8) * 4 + wn] = rmax[mi * 2 + 1];
            }
        }
        __syncthreads();
        if (tid < TILE_M) {
            float m = fmaxf(fmaxf(red[tid * 4 + 0], red[tid * 4 + 1]),
                            fmaxf(red[tid * 4 + 2], red[tid * 4 + 3]));
            atomicMax(&g_rowmax_enc[rowBase + tid], enc_f(m));
        }

        cur = nxt;
        abuf ^= 1;
    }

    // ---------------- Phase 2: last CTA out finalizes -----------------------
    __threadfence();
    __syncthreads();
    if (tid == 0) s_item = (atomicAdd(&g_done, 1) == GRID_PERS - 1) ? 1 : 0;
    __syncthreads();
    if (s_item) {
        __threadfence();   // acquire: all other CTAs' writes visible
        float* sum = (float*)(smem + SMEM_RED);
        float s = 0.0f;
        for (int b = tid; b < BSZ; b += 512)
            s += g_term1[b] + softplusf(dec_f(g_rowmax_enc[b]) - g_pos[b]);
        sum[tid] = s;
        __syncthreads();
        #pragma unroll
        for (int off = 256; off > 0; off >>= 1) {
            if (tid < off) sum[tid] += sum[tid + off];
            __syncthreads();
        }
        if (tid == 0) {
            out[0] = sum[0] / (2.0f * (float)BSZ);
            // reset counters for next graph replay
            g_ctr = 0; g_prep = 0; g_done = 0;
            __threadfence();
        }
    }
}

// ---------------------------------------------------------------------------
extern "C" void kernel_launch(void* const* d_in, const int* in_sizes, int n_in,
                              void* d_out, int out_size) {
    const float* q  = (const float*)d_in[0];
    const float* dd = (const float*)d_in[1];
    const float* nd = (const float*)d_in[2];
    float* out = (float*)d_out;

    cudaFuncSetAttribute(mega_kernel, cudaFuncAttributeMaxDynamicSharedMemorySize, SMEM_TOTAL);
    mega_kernel<<<GRID_PERS, 512, SMEM_TOTAL>>>(q, dd, nd, out);
}

// round 8
// speedup vs baseline: 1.0210x; 1.0210x over previous
#include <cuda_runtime.h>
#include <cuda_fp16.h>
#include <cstdint>

// ---------------------------------------------------------------------------
// Problem shape / tiling
// ---------------------------------------------------------------------------
#define BSZ    16384
#define DDIM   128
#define TILE_M 256               // rows per item
#define TILE_N 128               // cols per tile step
#define PITCH  272               // smem row pitch bytes (256 data + 16 pad)
#define NRT    (BSZ / TILE_M)    // 64 row tiles
#define NCHUNK 16                // col chunks per row tile (1024 cols)
#define NITEMS (NRT * NCHUNK)    // 1024 work items
#define CHUNK_TILES 8
#define GRID_PERS 148
#define NWARPS_G (GRID_PERS * 16)   // 2368 global warps
#define ROWS_PER_CTA 111            // ceil(16384/148)
#define NEGINF_LO 0x0000FC00u
#define NEGINF_HI 0xFC000000u

// Scratch (device globals; allocation-free rule)
__device__ __align__(128) __half g_Qh[BSZ * DDIM];   // 4 MB
__device__ __align__(128) __half g_Dh[BSZ * DDIM];   // 4 MB
__device__ float    g_pos[BSZ];
__device__ float    g_term1[BSZ];
__device__ unsigned g_rowmax_enc[BSZ];
__device__ float    g_part[160];
__device__ int      g_ctr;     // work-item counter
__device__ int      g_prep;    // grid barrier 1 (prep done)
__device__ int      g_done;    // grid barrier 2 (gemm done)
__device__ int      g_done2;   // grid barrier 3 (partials done)

// ---------------------------------------------------------------------------
// helpers
// ---------------------------------------------------------------------------
__device__ __forceinline__ uint32_t smem_to_u32(const void* p) {
    uint32_t a;
    asm("{ .reg .u64 t; cvta.to.shared.u64 t, %1; cvt.u32.u64 %0, t; }" : "=r"(a) : "l"(p));
    return a;
}
__device__ __forceinline__ void cpasync16(uint32_t s, const void* g) {
    asm volatile("cp.async.cg.shared.global [%0], [%1], 16;" :: "r"(s), "l"(g));
}
#define CP_COMMIT() asm volatile("cp.async.commit_group;" ::: "memory")
#define CP_WAIT0()  asm volatile("cp.async.wait_group 0;" ::: "memory")

__device__ __forceinline__ void ldsm4(uint32_t* r, uint32_t addr) {
    asm volatile("ldmatrix.sync.aligned.m8n8.x4.shared.b16 {%0,%1,%2,%3}, [%4];"
                 : "=r"(r[0]), "=r"(r[1]), "=r"(r[2]), "=r"(r[3]) : "r"(addr));
}
__device__ __forceinline__ void mma16816h(uint32_t* c, const uint32_t* a, uint32_t b0, uint32_t b1) {
    asm volatile("mma.sync.aligned.m16n8k16.row.col.f16.f16.f16.f16 "
                 "{%0,%1}, {%2,%3,%4,%5}, {%6,%7}, {%0,%1};"
                 : "+r"(c[0]), "+r"(c[1])
                 : "r"(a[0]), "r"(a[1]), "r"(a[2]), "r"(a[3]), "r"(b0), "r"(b1));
}
__device__ __forceinline__ uint32_t hmax2(uint32_t a, uint32_t b) {
    uint32_t d;
    asm("max.f16x2 %0, %1, %2;" : "=r"(d) : "r"(a), "r"(b));
    return d;
}
__device__ __forceinline__ float softplusf(float x) {
    return x > 20.0f ? x : log1pf(__expf(x));
}
__device__ __forceinline__ unsigned enc_f(float x) {
    unsigned u = __float_as_uint(x);
    return (u & 0x80000000u) ? ~u : (u | 0x80000000u);
}
__device__ __forceinline__ float dec_f(unsigned e) {
    unsigned u = (e & 0x80000000u) ? (e & 0x7FFFFFFFu) : ~e;
    return __uint_as_float(u);
}
__device__ __forceinline__ void spin_until(int* ctr, int target) {
    while (atomicAdd(ctr, 0) < target) { __nanosleep(64); }
}

// ---------------------------------------------------------------------------
// smem layout
// ---------------------------------------------------------------------------
#define SMEM_A0   0
#define SMEM_A1   (TILE_M * PITCH)                         // 69632
#define SMEM_B0   (2 * TILE_M * PITCH)                     // 139264
#define SMEM_B1   (2 * TILE_M * PITCH + 128 * PITCH)       // 174080
#define SMEM_RED  (2 * TILE_M * PITCH + 2 * 128 * PITCH)   // 208896
#define SMEM_TOTAL (SMEM_RED + TILE_M * 16)                // 212992 B

__device__ __forceinline__ void load_tileA(uint32_t dst, const __half* src,
                                           int rowBase, int tid) {
    const char* s = (const char*)(src + (size_t)rowBase * DDIM);
    #pragma unroll
    for (int i = 0; i < 8; ++i) {
        int e = tid + 512 * i;
        int r = e >> 4;
        int c = e & 15;
        cpasync16(dst + r * PITCH + c * 16, s + (size_t)r * 256 + c * 16);
    }
}
__device__ __forceinline__ void load_tileB(uint32_t dst, const __half* src,
                                           int rowBase, int tid) {
    const char* s = (const char*)(src + (size_t)rowBase * DDIM);
    #pragma unroll
    for (int i = 0; i < 4; ++i) {
        int e = tid + 512 * i;
        int r = e >> 4;
        int c = e & 15;
        cpasync16(dst + r * PITCH + c * 16, s + (size_t)r * 256 + c * 16);
    }
}

// ---------------------------------------------------------------------------
// ONE persistent kernel:
//   prep -> barrier -> max-GEMM -> barrier -> per-CTA partials -> last CTA out
// ---------------------------------------------------------------------------
__global__ void __launch_bounds__(512, 1)
mega_kernel(const float* __restrict__ q, const float* __restrict__ d,
            const float* __restrict__ nd, float* __restrict__ out) {
    extern __shared__ __align__(1024) char smem[];
    __shared__ int s_item;
    const uint32_t sb = smem_to_u32(smem);
    const int tid  = threadIdx.x;
    const int lane = tid & 31;
    const int wid  = tid >> 5;
    const int wm   = wid >> 2;        // 0..3
    const int wn   = wid & 3;         // 0..3

    // ---------------- Phase 0: prep (f32->f16, pairwise dots, init) --------
    {
        int gw = blockIdx.x * 16 + wid;   // global warp id 0..2367
        for (int row = gw; row < BSZ; row += NWARPS_G) {
            const float4 qv = *(const float4*)(q  + (size_t)row * DDIM + lane * 4);
            const float4 dv = *(const float4*)(d  + (size_t)row * DDIM + lane * 4);
            const float4 nv = *(const float4*)(nd + (size_t)row * DDIM + lane * 4);

            __half2* qdst = (__half2*)(g_Qh + (size_t)row * DDIM + lane * 4);
            qdst[0] = __floats2half2_rn(qv.x, qv.y);
            qdst[1] = __floats2half2_rn(qv.z, qv.w);
            __half2* ddst = (__half2*)(g_Dh + (size_t)row * DDIM + lane * 4);
            ddst[0] = __floats2half2_rn(dv.x, dv.y);
            ddst[1] = __floats2half2_rn(dv.z, dv.w);

            float pos = qv.x * dv.x + qv.y * dv.y + qv.z * dv.z + qv.w * dv.w;
            float neg = qv.x * nv.x + qv.y * nv.y + qv.z * nv.z + qv.w * nv.w;
            #pragma unroll
            for (int off = 16; off > 0; off >>= 1) {
                pos += __shfl_xor_sync(0xFFFFFFFFu, pos, off);
                neg += __shfl_xor_sync(0xFFFFFFFFu, neg, off);
            }
            if (lane == 0) {
                g_pos[row]   = pos;
                g_term1[row] = softplusf(neg - pos);
                g_rowmax_enc[row] = 0u;
            }
        }
    }
    // ---------------- grid barrier 1 ----------------------------------------
    __threadfence();
    __syncthreads();
    if (tid == 0) { atomicAdd(&g_prep, 1); spin_until(&g_prep, GRID_PERS); }
    __syncthreads();

    // ---------------- Phase 1: persistent max-GEMM (unchanged from R7) ------
    const uint32_t aOff  = (uint32_t)((wm * 64 + (lane & 15)) * PITCH + (lane & 16));
    const uint32_t bRow  = (uint32_t)(wn * 32 + ((lane >> 4) << 3) + (lane & 7));
    const uint32_t bOffC = (uint32_t)((lane & 8) << 1);
    float* red = (float*)(smem + SMEM_RED);   // [256][4]

    if (tid == 0) s_item = atomicAdd(&g_ctr, 1);
    __syncthreads();
    int cur = s_item;
    int abuf = 0;
    if (cur < NITEMS) {
        load_tileA(sb + SMEM_A0, g_Qh, (cur >> 4) * TILE_M, tid);
        load_tileB(sb + SMEM_B0, g_Dh, ((cur & 15) * CHUNK_TILES) * TILE_N, tid);
        CP_COMMIT();
    }

    while (cur < NITEMS) {
        const int rt = cur >> 4;
        const int cc = cur & 15;
        const int rowBase  = rt * TILE_M;
        const int tileBase = cc * CHUNK_TILES;
        const uint32_t aBase = sb + (abuf ? SMEM_A1 : SMEM_A0) + aOff;

        uint32_t rmax2[4][2];
        #pragma unroll
        for (int mi = 0; mi < 4; ++mi) { rmax2[mi][0] = 0xFC00FC00u; rmax2[mi][1] = 0xFC00FC00u; }

        int nxt = 0;
        for (int j = 0; j < CHUNK_TILES; ++j) {
            CP_WAIT0();
            __syncthreads();
            if (j + 1 < CHUNK_TILES) {
                uint32_t dst = sb + (((j + 1) & 1) ? SMEM_B1 : SMEM_B0);
                load_tileB(dst, g_Dh, (tileBase + j + 1) * TILE_N, tid);
                CP_COMMIT();
                if (j == CHUNK_TILES - 2 && tid == 0) s_item = atomicAdd(&g_ctr, 1);
            } else {
                nxt = s_item;
                if (nxt < NITEMS) {
                    load_tileA(sb + (abuf ? SMEM_A0 : SMEM_A1), g_Qh, (nxt >> 4) * TILE_M, tid);
                    load_tileB(sb + SMEM_B0, g_Dh, ((nxt & 15) * CHUNK_TILES) * TILE_N, tid);
                    CP_COMMIT();
                }
            }
            const uint32_t bBase = sb + ((j & 1) ? SMEM_B1 : SMEM_B0) + bRow * PITCH + bOffC;

            uint32_t acc[4][4][2];
            #pragma unroll
            for (int mi = 0; mi < 4; ++mi)
                #pragma unroll
                for (int ni = 0; ni < 4; ++ni) { acc[mi][ni][0] = 0u; acc[mi][ni][1] = 0u; }

            #pragma unroll
            for (int ks = 0; ks < 8; ++ks) {
                uint32_t a[4][4];
                #pragma unroll
                for (int mi = 0; mi < 4; ++mi)
                    ldsm4(a[mi], aBase + (uint32_t)(mi * 16 * PITCH + ks * 32));
                uint32_t b[2][4];
                #pragma unroll
                for (int np = 0; np < 2; ++np)
                    ldsm4(b[np], bBase + (uint32_t)(np * 16 * PITCH + ks * 32));
                #pragma unroll
                for (int mi = 0; mi < 4; ++mi)
                    #pragma unroll
                    for (int ni = 0; ni < 4; ++ni)
                        mma16816h(acc[mi][ni], a[mi],
                                  b[ni >> 1][(ni & 1) * 2], b[ni >> 1][(ni & 1) * 2 + 1]);
            }

            // diagonal: col tile hits diag when ct == 2*rt (rows 0..127) or 2*rt+1
            const int dt = (tileBase + j) - 2 * rt;
            if (dt == 0 || dt == 1) {
                const int coff = dt * 128;
                #pragma unroll
                for (int mi = 0; mi < 4; ++mi) {
                    int r0 = wm * 64 + mi * 16 + (lane >> 2);
                    #pragma unroll
                    for (int ni = 0; ni < 4; ++ni) {
                        int c0 = wn * 32 + ni * 8 + (lane & 3) * 2 + coff;
                        if (c0     == r0)     acc[mi][ni][0] = (acc[mi][ni][0] & 0xFFFF0000u) | NEGINF_LO;
                        if (c0 + 1 == r0)     acc[mi][ni][0] = (acc[mi][ni][0] & 0x0000FFFFu) | NEGINF_HI;
                        if (c0     == r0 + 8) acc[mi][ni][1] = (acc[mi][ni][1] & 0xFFFF0000u) | NEGINF_LO;
                        if (c0 + 1 == r0 + 8) acc[mi][ni][1] = (acc[mi][ni][1] & 0x0000FFFFu) | NEGINF_HI;
                    }
                }
            }
            #pragma unroll
            for (int mi = 0; mi < 4; ++mi)
                #pragma unroll
                for (int ni = 0; ni < 4; ++ni) {
                    rmax2[mi][0] = hmax2(rmax2[mi][0], acc[mi][ni][0]);
                    rmax2[mi][1] = hmax2(rmax2[mi][1], acc[mi][ni][1]);
                }
        }

        // epilogue: collapse + cross-warp reduce + atomicMax merge
        float rmax[8];
        #pragma unroll
        for (int mi = 0; mi < 4; ++mi)
            #pragma unroll
            for (int rr = 0; rr < 2; ++rr) {
                __half2 h = *(__half2*)&rmax2[mi][rr];
                rmax[mi * 2 + rr] = fmaxf(__low2float(h), __high2float(h));
            }
        #pragma unroll
        for (int i = 0; i < 8; ++i) {
            rmax[i] = fmaxf(rmax[i], __shfl_xor_sync(0xFFFFFFFFu, rmax[i], 1));
            rmax[i] = fmaxf(rmax[i], __shfl_xor_sync(0xFFFFFFFFu, rmax[i], 2));
        }
        __syncthreads();
        if ((lane & 3) == 0) {
            #pragma unroll
            for (int mi = 0; mi < 4; ++mi) {
                int rA = wm * 64 + mi * 16 + (lane >> 2);
                red[rA * 4 + wn]       = rmax[mi * 2 + 0];
                red[(rA + 8) * 4 + wn] = rmax[mi * 2 + 1];
            }
        }
        __syncthreads();
        if (tid < TILE_M) {
            float m = fmaxf(fmaxf(red[tid * 4 + 0], red[tid * 4 + 1]),
                            fmaxf(red[tid * 4 + 2], red[tid * 4 + 3]));
            atomicMax(&g_rowmax_enc[rowBase + tid], enc_f(m));
        }

        cur = nxt;
        abuf ^= 1;
    }

    // ---------------- grid barrier 2: all rowmax merges complete ------------
    __threadfence();
    __syncthreads();
    if (tid == 0) { atomicAdd(&g_done, 1); spin_until(&g_done, GRID_PERS); }
    __syncthreads();
    __threadfence();

    // ---------------- Phase 2a: per-CTA deterministic partial sum -----------
    {
        float* sum = (float*)(smem + SMEM_RED);   // 512 floats
        const int r0 = blockIdx.x * ROWS_PER_CTA;
        const int r1 = (r0 + ROWS_PER_CTA < BSZ) ? (r0 + ROWS_PER_CTA) : BSZ;
        float s = 0.0f;
        for (int b = r0 + tid; b < r1; b += 512)
            s += g_term1[b] + softplusf(dec_f(g_rowmax_enc[b]) - g_pos[b]);
        sum[tid] = s;
        __syncthreads();
        #pragma unroll
        for (int off = 256; off > 0; off >>= 1) {
            if (tid < off) sum[tid] += sum[tid + off];
            __syncthreads();
        }
        if (tid == 0) { g_part[blockIdx.x] = sum[0]; __threadfence(); }
    }

    // ---------------- Phase 2b: last CTA combines 148 partials --------------
    __syncthreads();
    if (tid == 0) s_item = (atomicAdd(&g_done2, 1) == GRID_PERS - 1) ? 1 : 0;
    __syncthreads();
    if (s_item) {
        __threadfence();   // acquire all g_part writes
        float* sum = (float*)(smem + SMEM_RED);
        sum[tid] = (tid < GRID_PERS) ? g_part[tid] : 0.0f;
        __syncthreads();
        #pragma unroll
        for (int off = 256; off > 0; off >>= 1) {
            if (tid < off) sum[tid] += sum[tid + off];
            __syncthreads();
        }
        if (tid == 0) {
            out[0] = sum[0] / (2.0f * (float)BSZ);
            // reset counters for next graph replay
            g_ctr = 0; g_prep = 0; g_done = 0; g_done2 = 0;
            __threadfence();
        }
    }
}

// ---------------------------------------------------------------------------
extern "C" void kernel_launch(void* const* d_in, const int* in_sizes, int n_in,
                              void* d_out, int out_size) {
    const float* q  = (const float*)d_in[0];
    const float* dd = (const float*)d_in[1];
    const float* nd = (const float*)d_in[2];
    float* out = (float*)d_out;

    cudaFuncSetAttribute(mega_kernel, cudaFuncAttributeMaxDynamicSharedMemorySize, SMEM_TOTAL);
    mega_kernel<<<GRID_PERS, 512, SMEM_TOTAL>>>(q, dd, nd, out);
}

// round 9
// speedup vs baseline: 1.0332x; 1.0119x over previous
#include <cuda_runtime.h>
#include <cuda_fp16.h>
#include <cstdint>

// ---------------------------------------------------------------------------
// Problem shape / tiling
// ---------------------------------------------------------------------------
#define BSZ    16384
#define DDIM   128
#define TILE_M 256               // rows per item
#define TILE_N 128               // cols per tile step
#define NRT    (BSZ / TILE_M)    // 64 row tiles
#define NCHUNK 16                // col chunks per row tile (1024 cols)
#define NITEMS (NRT * NCHUNK)    // 1024 work items
#define CHUNK_TILES 8
#define GRID_PERS 148
#define NWARPS_G (GRID_PERS * 16)
#define ROWS_PER_CTA 111
#define NEGINF_LO 0x0000FC00u
#define NEGINF_HI 0xFC000000u

// Scratch (device globals; allocation-free rule)
__device__ __align__(128) __half g_Qh[BSZ * DDIM];   // 4 MB
__device__ __align__(128) __half g_Dh[BSZ * DDIM];   // 4 MB
__device__ float    g_pos[BSZ];
__device__ float    g_term1[BSZ];
__device__ unsigned g_rowmax_enc[BSZ];
__device__ float    g_part[160];
__device__ int      g_ctr;
__device__ int      g_prep;
__device__ int      g_done;
__device__ int      g_done2;

// ---------------------------------------------------------------------------
// helpers
// ---------------------------------------------------------------------------
__device__ __forceinline__ uint32_t smem_to_u32(const void* p) {
    uint32_t a;
    asm("{ .reg .u64 t; cvta.to.shared.u64 t, %1; cvt.u32.u64 %0, t; }" : "=r"(a) : "l"(p));
    return a;
}
__device__ __forceinline__ void cpasync16(uint32_t s, const void* g) {
    asm volatile("cp.async.cg.shared.global [%0], [%1], 16;" :: "r"(s), "l"(g));
}
#define CP_COMMIT() asm volatile("cp.async.commit_group;" ::: "memory")
#define CP_WAIT0()  asm volatile("cp.async.wait_group 0;" ::: "memory")
#define CP_WAIT1()  asm volatile("cp.async.wait_group 1;" ::: "memory")

__device__ __forceinline__ void ldsm4(uint32_t* r, uint32_t addr) {
    asm volatile("ldmatrix.sync.aligned.m8n8.x4.shared.b16 {%0,%1,%2,%3}, [%4];"
                 : "=r"(r[0]), "=r"(r[1]), "=r"(r[2]), "=r"(r[3]) : "r"(addr));
}
__device__ __forceinline__ void mma16816h(uint32_t* c, const uint32_t* a, uint32_t b0, uint32_t b1) {
    asm volatile("mma.sync.aligned.m16n8k16.row.col.f16.f16.f16.f16 "
                 "{%0,%1}, {%2,%3,%4,%5}, {%6,%7}, {%0,%1};"
                 : "+r"(c[0]), "+r"(c[1])
                 : "r"(a[0]), "r"(a[1]), "r"(a[2]), "r"(a[3]), "r"(b0), "r"(b1));
}
__device__ __forceinline__ uint32_t hmax2(uint32_t a, uint32_t b) {
    uint32_t d;
    asm("max.f16x2 %0, %1, %2;" : "=r"(d) : "r"(a), "r"(b));
    return d;
}
__device__ __forceinline__ float softplusf(float x) {
    return x > 20.0f ? x : log1pf(__expf(x));
}
__device__ __forceinline__ unsigned enc_f(float x) {
    unsigned u = __float_as_uint(x);
    return (u & 0x80000000u) ? ~u : (u | 0x80000000u);
}
__device__ __forceinline__ float dec_f(unsigned e) {
    unsigned u = (e & 0x80000000u) ? (e & 0x7FFFFFFFu) : ~e;
    return __uint_as_float(u);
}
__device__ __forceinline__ void spin_until(int* ctr, int target) {
    while (atomicAdd(ctr, 0) < target) { __nanosleep(64); }
}

// ---------------------------------------------------------------------------
// smem layout: A x2 (256 rows x 256B), B ring x3 (128 rows x 256B). Swizzled.
// ---------------------------------------------------------------------------
#define SMEM_A0    0
#define SMEM_A1    65536
#define SMEM_BR    131072          // + slot * 32768, 3 slots
#define SMEM_TOTAL 229376

// swizzle: 16B chunk c of row r lives at chunk (c ^ (r & 7))
__device__ __forceinline__ void load_tileA_sw(uint32_t dst, const __half* src,
                                              int rowBase, int tid) {
    const char* s = (const char*)(src + (size_t)rowBase * DDIM);
    #pragma unroll
    for (int i = 0; i < 8; ++i) {
        int e = tid + 512 * i;         // 4096 chunks (256 rows x 16)
        int r = e >> 4;
        int c = e & 15;
        cpasync16(dst + r * 256 + ((c ^ (r & 7)) << 4), s + (size_t)r * 256 + c * 16);
    }
}
__device__ __forceinline__ void load_tileB_sw(uint32_t dst, const __half* src,
                                              int rowBase, int tid) {
    const char* s = (const char*)(src + (size_t)rowBase * DDIM);
    #pragma unroll
    for (int i = 0; i < 4; ++i) {
        int e = tid + 512 * i;         // 2048 chunks (128 rows x 16)
        int r = e >> 4;
        int c = e & 15;
        cpasync16(dst + r * 256 + ((c ^ (r & 7)) << 4), s + (size_t)r * 256 + c * 16);
    }
}

// ---------------------------------------------------------------------------
// ONE persistent kernel
// ---------------------------------------------------------------------------
__global__ void __launch_bounds__(512, 1)
mega_kernel(const float* __restrict__ q, const float* __restrict__ d,
            const float* __restrict__ nd, float* __restrict__ out) {
    extern __shared__ __align__(1024) char smem[];
    __shared__ int s_item;
    const uint32_t sb = smem_to_u32(smem);
    const int tid  = threadIdx.x;
    const int lane = tid & 31;
    const int wid  = tid >> 5;
    const int wm   = wid >> 2;        // 0..3
    const int wn   = wid & 3;         // 0..3

    // ---------------- Phase 0: prep ----------------------------------------
    {
        int gw = blockIdx.x * 16 + wid;
        for (int row = gw; row < BSZ; row += NWARPS_G) {
            const float4 qv = *(const float4*)(q  + (size_t)row * DDIM + lane * 4);
            const float4 dv = *(const float4*)(d  + (size_t)row * DDIM + lane * 4);
            const float4 nv = *(const float4*)(nd + (size_t)row * DDIM + lane * 4);

            __half2* qdst = (__half2*)(g_Qh + (size_t)row * DDIM + lane * 4);
            qdst[0] = __floats2half2_rn(qv.x, qv.y);
            qdst[1] = __floats2half2_rn(qv.z, qv.w);
            __half2* ddst = (__half2*)(g_Dh + (size_t)row * DDIM + lane * 4);
            ddst[0] = __floats2half2_rn(dv.x, dv.y);
            ddst[1] = __floats2half2_rn(dv.z, dv.w);

            float pos = qv.x * dv.x + qv.y * dv.y + qv.z * dv.z + qv.w * dv.w;
            float neg = qv.x * nv.x + qv.y * nv.y + qv.z * nv.z + qv.w * nv.w;
            #pragma unroll
            for (int off = 16; off > 0; off >>= 1) {
                pos += __shfl_xor_sync(0xFFFFFFFFu, pos, off);
                neg += __shfl_xor_sync(0xFFFFFFFFu, neg, off);
            }
            if (lane == 0) {
                g_pos[row]   = pos;
                g_term1[row] = softplusf(neg - pos);
                g_rowmax_enc[row] = 0u;
            }
        }
    }
    __threadfence();
    __syncthreads();
    if (tid == 0) { atomicAdd(&g_prep, 1); spin_until(&g_prep, GRID_PERS); }
    __syncthreads();

    // ---------------- Phase 1: pipelined persistent max-GEMM ----------------
    const int xr  = lane & 7;                 // swizzle xor value for this lane
    const int hcA = (lane >> 4) & 1;          // A high-chunk bit
    const int hcB = (lane >> 3) & 1;          // B high-chunk bit
    const uint32_t aRow    = (uint32_t)((wm * 64 + (lane & 15)) * 256);
    const uint32_t bRowOff = (uint32_t)((wn * 32 + ((lane >> 4) << 3) + (lane & 7)) * 256);

    if (tid == 0) s_item = atomicAdd(&g_ctr, 1);
    __syncthreads();
    int cur = s_item;
    int abuf = 0, slotc = 0, j = 0;
    int nxt = NITEMS;
    int rt = cur >> 4, cc8 = (cur & 15) * CHUNK_TILES, rowBase = rt * TILE_M;

    uint32_t rmax2[4][2];
    #pragma unroll
    for (int mi = 0; mi < 4; ++mi) { rmax2[mi][0] = 0xFC00FC00u; rmax2[mi][1] = 0xFC00FC00u; }

    if (cur < NITEMS) {
        load_tileA_sw(sb + SMEM_A0, g_Qh, rowBase, tid);
        load_tileB_sw(sb + SMEM_BR, g_Dh, (cc8 + 0) * TILE_N, tid);
        CP_COMMIT();
        load_tileB_sw(sb + SMEM_BR + 32768, g_Dh, (cc8 + 1) * TILE_N, tid);
        CP_COMMIT();
    }

    while (cur < NITEMS) {
        CP_WAIT1();
        __syncthreads();
        if (j >= 5) nxt = s_item;

        // prefetch tile seq+2 (always commit a group, possibly empty)
        {
            int pf = j + 2;
            uint32_t dstB = sb + SMEM_BR + (uint32_t)(((slotc + 2) % 3) * 32768);
            if (pf < CHUNK_TILES) {
                load_tileB_sw(dstB, g_Dh, (cc8 + pf) * TILE_N, tid);
            } else if (nxt < NITEMS) {
                if (pf == CHUNK_TILES) {
                    load_tileA_sw(sb + (abuf ? SMEM_A0 : SMEM_A1), g_Qh, (nxt >> 4) * TILE_M, tid);
                    load_tileB_sw(dstB, g_Dh, ((nxt & 15) * CHUNK_TILES + 0) * TILE_N, tid);
                } else {
                    load_tileB_sw(dstB, g_Dh, ((nxt & 15) * CHUNK_TILES + 1) * TILE_N, tid);
                }
            }
            CP_COMMIT();
        }
        if (j == 4 && tid == 0) s_item = atomicAdd(&g_ctr, 1);

        // compute tile (cur, j)
        const uint32_t aBufBase = sb + (abuf ? SMEM_A1 : SMEM_A0) + aRow;
        const uint32_t bBufBase = sb + SMEM_BR + (uint32_t)(slotc * 32768) + bRowOff;

        uint32_t acc[4][4][2];
        #pragma unroll
        for (int mi = 0; mi < 4; ++mi)
            #pragma unroll
            for (int ni = 0; ni < 4; ++ni) { acc[mi][ni][0] = 0u; acc[mi][ni][1] = 0u; }

        #pragma unroll
        for (int ks = 0; ks < 8; ++ks) {
            const uint32_t aCh = (uint32_t)(((ks * 2 + hcA) ^ xr) << 4);
            const uint32_t bCh = (uint32_t)(((ks * 2 + hcB) ^ xr) << 4);
            uint32_t a[4][4];
            #pragma unroll
            for (int mi = 0; mi < 4; ++mi)
                ldsm4(a[mi], aBufBase + (uint32_t)(mi * 4096) + aCh);
            uint32_t b[2][4];
            #pragma unroll
            for (int np = 0; np < 2; ++np)
                ldsm4(b[np], bBufBase + (uint32_t)(np * 4096) + bCh);
            #pragma unroll
            for (int mi = 0; mi < 4; ++mi)
                #pragma unroll
                for (int ni = 0; ni < 4; ++ni)
                    mma16816h(acc[mi][ni], a[mi],
                              b[ni >> 1][(ni & 1) * 2], b[ni >> 1][(ni & 1) * 2 + 1]);
        }

        // diagonal mask: col tile hits diag when ct == 2*rt (+0) or 2*rt+1 (+1)
        {
            const int dt = (cc8 + j) - 2 * rt;
            if (dt == 0 || dt == 1) {
                const int coff = dt * 128;
                #pragma unroll
                for (int mi = 0; mi < 4; ++mi) {
                    int r0 = wm * 64 + mi * 16 + (lane >> 2);
                    #pragma unroll
                    for (int ni = 0; ni < 4; ++ni) {
                        int c0 = wn * 32 + ni * 8 + (lane & 3) * 2 + coff;
                        if (c0     == r0)     acc[mi][ni][0] = (acc[mi][ni][0] & 0xFFFF0000u) | NEGINF_LO;
                        if (c0 + 1 == r0)     acc[mi][ni][0] = (acc[mi][ni][0] & 0x0000FFFFu) | NEGINF_HI;
                        if (c0     == r0 + 8) acc[mi][ni][1] = (acc[mi][ni][1] & 0xFFFF0000u) | NEGINF_LO;
                        if (c0 + 1 == r0 + 8) acc[mi][ni][1] = (acc[mi][ni][1] & 0x0000FFFFu) | NEGINF_HI;
                    }
                }
            }
        }
        #pragma unroll
        for (int mi = 0; mi < 4; ++mi)
            #pragma unroll
            for (int ni = 0; ni < 4; ++ni) {
                rmax2[mi][0] = hmax2(rmax2[mi][0], acc[mi][ni][0]);
                rmax2[mi][1] = hmax2(rmax2[mi][1], acc[mi][ni][1]);
            }

        ++j;
        slotc = (slotc == 2) ? 0 : slotc + 1;

        if (j == CHUNK_TILES) {
            // item epilogue: collapse + quad reduce + direct atomicMax (4/row)
            float rmax[8];
            #pragma unroll
            for (int mi = 0; mi < 4; ++mi)
                #pragma unroll
                for (int rr = 0; rr < 2; ++rr) {
                    __half2 h = *(__half2*)&rmax2[mi][rr];
                    rmax[mi * 2 + rr] = fmaxf(__low2float(h), __high2float(h));
                }
            #pragma unroll
            for (int i = 0; i < 8; ++i) {
                rmax[i] = fmaxf(rmax[i], __shfl_xor_sync(0xFFFFFFFFu, rmax[i], 1));
                rmax[i] = fmaxf(rmax[i], __shfl_xor_sync(0xFFFFFFFFu, rmax[i], 2));
            }
            if ((lane & 3) == 0) {
                #pragma unroll
                for (int mi = 0; mi < 4; ++mi) {
                    int rA = rowBase + wm * 64 + mi * 16 + (lane >> 2);
                    atomicMax(&g_rowmax_enc[rA],     enc_f(rmax[mi * 2 + 0]));
                    atomicMax(&g_rowmax_enc[rA + 8], enc_f(rmax[mi * 2 + 1]));
                }
            }
            // advance to next item
            cur = nxt;
            abuf ^= 1;
            j = 0;
            if (cur < NITEMS) {
                rt = cur >> 4; cc8 = (cur & 15) * CHUNK_TILES; rowBase = rt * TILE_M;
                nxt = NITEMS;
                #pragma unroll
                for (int mi = 0; mi < 4; ++mi) { rmax2[mi][0] = 0xFC00FC00u; rmax2[mi][1] = 0xFC00FC00u; }
            }
        }
    }
    CP_WAIT0();

    // ---------------- grid barrier 2 ----------------------------------------
    __threadfence();
    __syncthreads();
    if (tid == 0) { atomicAdd(&g_done, 1); spin_until(&g_done, GRID_PERS); }
    __syncthreads();
    __threadfence();

    // ---------------- Phase 2a: per-CTA deterministic partial sum -----------
    {
        float* sum = (float*)smem;   // A region is dead now
        const int r0 = blockIdx.x * ROWS_PER_CTA;
        const int r1 = (r0 + ROWS_PER_CTA < BSZ) ? (r0 + ROWS_PER_CTA) : BSZ;
        float s = 0.0f;
        for (int b = r0 + tid; b < r1; b += 512)
            s += g_term1[b] + softplusf(dec_f(g_rowmax_enc[b]) - g_pos[b]);
        sum[tid] = s;
        __syncthreads();
        #pragma unroll
        for (int off = 256; off > 0; off >>= 1) {
            if (tid < off) sum[tid] += sum[tid + off];
            __syncthreads();
        }
        if (tid == 0) { g_part[blockIdx.x] = sum[0]; __threadfence(); }
    }

    // ---------------- Phase 2b: last CTA combines ---------------------------
    __syncthreads();
    if (tid == 0) s_item = (atomicAdd(&g_done2, 1) == GRID_PERS - 1) ? 1 : 0;
    __syncthreads();
    if (s_item) {
        __threadfence();
        float* sum = (float*)smem;
        sum[tid] = (tid < GRID_PERS) ? g_part[tid] : 0.0f;
        __syncthreads();
        #pragma unroll
        for (int off = 256; off > 0; off >>= 1) {
            if (tid < off) sum[tid] += sum[tid + off];
            __syncthreads();
        }
        if (tid == 0) {
            out[0] = sum[0] / (2.0f * (float)BSZ);
            g_ctr = 0; g_prep = 0; g_done = 0; g_done2 = 0;
            __threadfence();
        }
    }
}

// ---------------------------------------------------------------------------
extern "C" void kernel_launch(void* const* d_in, const int* in_sizes, int n_in,
                              void* d_out, int out_size) {
    const float* q  = (const float*)d_in[0];
    const float* dd = (const float*)d_in[1];
    const float* nd = (const float*)d_in[2];
    float* out = (float*)d_out;

    cudaFuncSetAttribute(mega_kernel, cudaFuncAttributeMaxDynamicSharedMemorySize, SMEM_TOTAL);
    mega_kernel<<<GRID_PERS, 512, SMEM_TOTAL>>>(q, dd, nd, out);
}